// round 14
// baseline (speedup 1.0000x reference)
#include <cuda_runtime.h>
#include <cstdint>

// ASG loss = FCC (log-partition over all paths) - FAC (forced alignment).
// T=512, B=32, V=512, L=128 (fixed by dataset).
//
// FCC: unnormalized probability recursion v' = exp(lp) * (E v), E in regs.
// Cluster of 8 CTAs per 2 batches. Per-step exchange: SELF-SIGNALING
// st.async scalar stores (protocol byte-identical to the 825us best:
// 2 tx-barriers, expect_tx=4096B, parity ((t-1)>>1)&1, re-arm after
// consume, 1024 messages/dest/step).
// Source-side critical path shortened vs the 825us kernel: each thread
// owns ONE row x 64 contiguous j's of E (same 64-float budget); a row's
// 8 owning lanes reduce via a 3-round butterfly (xor 4/8/16), leaving
// every lane with both batches' row sums; lane (s,rr) then pushes row
// rr's two values to rank s: 2 STAS per lane, spread over all 32 lanes.
// (R13's bug: Phase A covered only half the j's -> v underflow -> inf.
//  Fixed here: all 16 floats per q-stride are loaded and consumed.)
// FAC: separate CTAs, 1 warp/batch, register-resident.

namespace {
constexpr int T_ = 512, B_ = 32, V_ = 512, L_ = 128;
constexpr int CSZ = 8;      // cluster size
constexpr int ISL = 64;     // i-rows per CTA
constexpr int NTHR = 512;
constexpr int NFCC = 16;    // FCC clusters (2 batches each)
constexpr float NEG = -1000000000.0f;
constexpr unsigned FILL_BYTES = 2u * V_ * 4u;   // 4096 B per fill
}

__device__ float g_fcc[B_];
__device__ float g_fac[B_];
__device__ unsigned g_done[B_];   // parity counter, never reset

static __device__ __forceinline__ unsigned cta_rank() {
    unsigned r; asm("mov.u32 %0, %%cluster_ctarank;" : "=r"(r)); return r;
}
static __device__ __forceinline__ unsigned su32(const void* p) {
    unsigned a;
    asm("{ .reg .u64 t; cvta.to.shared.u64 t, %1; cvt.u32.u64 %0, t; }"
        : "=r"(a) : "l"(p));
    return a;
}
static __device__ __forceinline__ unsigned mapa_r(unsigned a, unsigned r) {
    unsigned o;
    asm("mapa.shared::cluster.u32 %0, %1, %2;" : "=r"(o) : "r"(a), "r"(r));
    return o;
}
static __device__ __forceinline__ void csync() {
    asm volatile("barrier.cluster.arrive.aligned;" ::: "memory");
    asm volatile("barrier.cluster.wait.aligned;" ::: "memory");
}
static __device__ __forceinline__ void mbar_init(unsigned a, unsigned cnt) {
    asm volatile("mbarrier.init.shared.b64 [%0], %1;" :: "r"(a), "r"(cnt) : "memory");
}
static __device__ __forceinline__ void mbar_expect(unsigned a, unsigned tx) {
    asm volatile("mbarrier.arrive.expect_tx.shared.b64 _, [%0], %1;"
                 :: "r"(a), "r"(tx) : "memory");
}
// Self-signaling remote store: data lands in peer SMEM, credits 4 bytes on
// the peer's mbarrier when complete.
static __device__ __forceinline__ void st_async32(unsigned a, float v, unsigned mb) {
    asm volatile("st.async.shared::cluster.mbarrier::complete_tx::bytes.b32 [%0], %1, [%2];"
                 :: "r"(a), "r"(__float_as_uint(v)), "r"(mb) : "memory");
}
static __device__ __forceinline__ void mbar_wait(unsigned a, unsigned parity) {
    unsigned done;
    asm volatile(
        "{\n\t.reg .pred p;\n\t"
        "mbarrier.try_wait.parity.acquire.cluster.shared::cta.b64 p, [%1], %2;\n\t"
        "selp.b32 %0, 1, 0, p;\n\t}"
        : "=r"(done) : "r"(a), "r"(parity) : "memory");
    if (!done) {
        asm volatile(
            "{\n\t.reg .pred P1;\n\t"
            "WL_%=:\n\t"
            "mbarrier.try_wait.parity.acquire.cluster.shared::cta.b64 P1, [%0], %1, 0x989680;\n\t"
            "@P1 bra.uni WD_%=;\n\t"
            "bra.uni WL_%=;\n\t"
            "WD_%=:\n\t}"
            :: "r"(a), "r"(parity) : "memory");
    }
}
static __device__ __forceinline__ unsigned long long fma2(
    unsigned long long a, unsigned long long b, unsigned long long c) {
    unsigned long long d;
    asm("fma.rn.f32x2 %0, %1, %2, %3;" : "=l"(d) : "l"(a), "l"(b), "l"(c));
    return d;
}
static __device__ __forceinline__ unsigned long long addf2(
    unsigned long long a, unsigned long long b) {
    unsigned long long d;
    asm("add.rn.f32x2 %0, %1, %2;" : "=l"(d) : "l"(a), "l"(b));
    return d;
}
static __device__ __forceinline__ unsigned long long packf2(float lo, float hi) {
    unsigned long long d;
    asm("mov.b64 %0, {%1,%2};" : "=l"(d) : "f"(lo), "f"(hi));
    return d;
}
static __device__ __forceinline__ float pairsum(unsigned long long a) {
    float lo, hi;
    asm("mov.b64 {%0,%1}, %2;" : "=f"(lo), "=f"(hi) : "l"(a));
    return lo + hi;
}

// Second arriver (parity odd) of {fcc, fac} writes the output.
static __device__ __forceinline__ void publish(int b, float val, bool is_fcc,
                                               float* __restrict__ out) {
    if (is_fcc) g_fcc[b] = val; else g_fac[b] = val;
    __threadfence();
    unsigned old = atomicAdd(&g_done[b], 1u);
    if (old & 1u) {
        __threadfence();
        out[b] = g_fcc[b] - g_fac[b];
    }
}

__global__ void __launch_bounds__(NTHR, 1) __cluster_dims__(CSZ, 1, 1)
asg_main(const float* __restrict__ lp, const float* __restrict__ tr,
         const int* __restrict__ tgt, const int* __restrict__ ilen,
         const int* __restrict__ tlen, float* __restrict__ out)
{
    __shared__ __align__(16) float s_u[2][2][V_];        // double-buffered v
    __shared__ __align__(8) unsigned long long s_mbar[2];

    const int tid  = threadIdx.x;
    const int lane = tid & 31;
    const int wid  = tid >> 5;
    const int cid  = (int)blockIdx.x >> 3;

    if (cid < NFCC) {
        // =============================== FCC ===============================
        const unsigned r = cta_rank();
        const int b0 = 2 * cid, b1 = 2 * cid + 1;
        const int len0 = ilen[b0], len1 = ilen[b1];

        // Thread role: s = lane>>2 (j-slice / push rank), rr = lane&3 (row).
        const int s_  = lane >> 2;
        const int rr  = lane & 3;
        const int prow = (int)r * ISL + wid * 4 + rr;    // this thread's row
        const int js   = 64 * s_;                         // this thread's j base

        const unsigned ubase  = su32(&s_u[0][0][0]);
        const unsigned mloc0  = su32(&s_mbar[0]);
        const unsigned mdelta = mloc0 - ubase;
        const unsigned pbS    = mapa_r(ubase, (unsigned)s_);   // push rank base

        if (tid == 0) {
            mbar_init(mloc0, 1);
            mbar_init(mloc0 + 8, 1);
            mbar_expect(mloc0 + 8, FILL_BYTES);   // fill@t=0 targets mbar[1]
        }

        // E registers: one row (prow), j in [js, js+64). 32 u64 (64 floats).
        // e2[2m], e2[2m+1] cover j = js+4m .. js+4m+3.
        unsigned long long e2[32];
        {
            const float* trow = tr + (size_t)prow * V_ + js;
            #pragma unroll
            for (int m = 0; m < 16; ++m) {
                float4 v4 = *(const float4*)(trow + 4 * m);
                e2[2 * m]     = packf2(__expf(v4.x), __expf(v4.y));
                e2[2 * m + 1] = packf2(__expf(v4.z), __expf(v4.w));
            }
        }

        // v_0 = exp(lp[0,b,:]); every CTA initializes buffer 0 locally.
        s_u[0][0][tid] = __expf(lp[(size_t)b0 * V_ + tid]);
        s_u[0][1][tid] = __expf(lp[(size_t)b1 * V_ + tid]);
        __syncthreads();
        csync();   // peers' mbar init + expect + buffers visible

        for (int t = 0; t < T_; ++t) {
            const int buf = t & 1;

            // Prefetch exp(lp[t+1]) for this thread's row, both batches
            float el0 = 0.f, el1 = 0.f;
            if (t + 1 < T_) {
                el0 = __expf(lp[((size_t)(t + 1) * B_ + b0) * V_ + prow]);
                el1 = __expf(lp[((size_t)(t + 1) * B_ + b1) * V_ + prow]);
            }

            if (t) mbar_wait(mloc0 + (unsigned)buf * 8, (unsigned)(((t - 1) >> 1) & 1));

            // Arm this mbar for its next fill (fill@t+1), after its consume
            if (tid == 0 && t + 3 <= T_)
                mbar_expect(mloc0 + (unsigned)buf * 8, FILL_BYTES);

            // Score capture (once per batch): lse(alpha_t) = log sum_j v_j
            if (r == 0 && (wid == 8 || wid == 9)) {
                const int bs = wid - 8;
                if (t == (bs ? len1 : len0) - 1) {
                    float sc = 0.f;
                    #pragma unroll
                    for (int k = 0; k < 16; ++k) sc += s_u[buf][bs][lane + 32 * k];
                    #pragma unroll
                    for (int mk = 16; mk; mk >>= 1) sc += __shfl_xor_sync(~0u, sc, mk);
                    if (lane == 0) publish(bs ? b1 : b0, logf(sc), true, out);
                }
            }
            if (t == T_ - 1) break;

            // Phase A: full 64-j dot for this thread's single row, both
            // batches. Per q: 16 floats = 4 ulonglong2 loads, e2[8q..8q+7].
            // Quad lanes (same s_) broadcast-load identical addresses.
            unsigned long long a0q[4], a1q[4];
            #pragma unroll
            for (int q = 0; q < 4; ++q) { a0q[q] = 0ull; a1q[q] = 0ull; }
            #pragma unroll
            for (int q = 0; q < 4; ++q) {
                const ulonglong2* p0 = (const ulonglong2*)&s_u[buf][0][js + 16 * q];
                const ulonglong2* p1 = (const ulonglong2*)&s_u[buf][1][js + 16 * q];
                ulonglong2 u0 = p0[0], u1 = p0[1], u2 = p0[2], u3 = p0[3];
                ulonglong2 w0 = p1[0], w1 = p1[1], w2 = p1[2], w3 = p1[3];
                a0q[q] = fma2(e2[8 * q],     u0.x, a0q[q]);
                a0q[q] = fma2(e2[8 * q + 1], u0.y, a0q[q]);
                a0q[q] = fma2(e2[8 * q + 2], u1.x, a0q[q]);
                a0q[q] = fma2(e2[8 * q + 3], u1.y, a0q[q]);
                a0q[q] = fma2(e2[8 * q + 4], u2.x, a0q[q]);
                a0q[q] = fma2(e2[8 * q + 5], u2.y, a0q[q]);
                a0q[q] = fma2(e2[8 * q + 6], u3.x, a0q[q]);
                a0q[q] = fma2(e2[8 * q + 7], u3.y, a0q[q]);
                a1q[q] = fma2(e2[8 * q],     w0.x, a1q[q]);
                a1q[q] = fma2(e2[8 * q + 1], w0.y, a1q[q]);
                a1q[q] = fma2(e2[8 * q + 2], w1.x, a1q[q]);
                a1q[q] = fma2(e2[8 * q + 3], w1.y, a1q[q]);
                a1q[q] = fma2(e2[8 * q + 4], w2.x, a1q[q]);
                a1q[q] = fma2(e2[8 * q + 5], w2.y, a1q[q]);
                a1q[q] = fma2(e2[8 * q + 6], w3.x, a1q[q]);
                a1q[q] = fma2(e2[8 * q + 7], w3.y, a1q[q]);
            }
            float p0s = pairsum(addf2(addf2(a0q[0], a0q[1]), addf2(a0q[2], a0q[3])));
            float p1s = pairsum(addf2(addf2(a1q[0], a1q[1]), addf2(a1q[2], a1q[3])));

            // Butterfly over the row's 8 owning lanes (xor 4,8,16): every
            // lane ends with the full row sums for both batches.
            #pragma unroll
            for (int mk = 4; mk <= 16; mk <<= 1) {
                p0s += __shfl_xor_sync(~0u, p0s, mk);
                p1s += __shfl_xor_sync(~0u, p1s, mk);
            }

            // Push: lane (s,rr) sends row rr's two batch values to rank s.
            {
                const float v0 = el0 * p0s;
                const float v1 = el1 * p1s;
                const int nbuf = buf ^ 1;
                const unsigned off0 = ((unsigned)(nbuf * 2) * V_ + (unsigned)prow) * 4u;
                const unsigned mb = pbS + mdelta + (unsigned)nbuf * 8u;
                st_async32(pbS + off0, v0, mb);
                st_async32(pbS + off0 + V_ * 4u, v1, mb);
            }
        }
        csync();   // no CTA exits while peers may still write its SMEM
    } else {
        // =============================== FAC ===============================
        if (wid >= 4) return;
        const int b = ((int)blockIdx.x - NFCC * CSZ) * 4 + wid;   // 0..31
        const int il = ilen[b], tl = tlen[b];

        int tg[4];
        #pragma unroll
        for (int k = 0; k < 4; ++k) tg[k] = tgt[b * L_ + lane * 4 + k];

        float ts[4], tp[4];
        #pragma unroll
        for (int k = 0; k < 4; ++k) ts[k] = tr[tg[k] * V_ + tg[k]];
        const int tprev = __shfl_up_sync(~0u, tg[3], 1);
        tp[0] = tr[tg[0] * V_ + tprev];           // garbage on lane 0, never used
        tp[1] = tr[tg[1] * V_ + tg[0]];
        tp[2] = tr[tg[2] * V_ + tg[1]];
        tp[3] = tr[tg[3] * V_ + tg[2]];

        float beta[4];
        #pragma unroll
        for (int k = 0; k < 4; ++k)
            beta[k] = (lane == 0 && k == 0) ? lp[(size_t)b * V_ + tg[0]] : NEG;

        float emn[4];
        #pragma unroll
        for (int k = 0; k < 4; ++k)
            emn[k] = lp[((size_t)1 * B_ + b) * V_ + tg[k]];

        for (int t = 0; t < T_; ++t) {
            if (t == il - 1) {
                const int lsel = tl - 1;
                if (lane == (lsel >> 2)) publish(b, beta[lsel & 3], false, out);
            }
            if (t == T_ - 1) break;

            float em[4];
            #pragma unroll
            for (int k = 0; k < 4; ++k) em[k] = emn[k];
            if (t + 2 < T_) {
                #pragma unroll
                for (int k = 0; k < 4; ++k)
                    emn[k] = lp[((size_t)(t + 2) * B_ + b) * V_ + tg[k]];
            }

            const float bprev = __shfl_up_sync(~0u, beta[3], 1);
            float prevs[4] = {bprev, beta[0], beta[1], beta[2]};
            #pragma unroll
            for (int k = 0; k < 4; ++k) {
                float stay = beta[k] + ts[k];
                float move = (lane == 0 && k == 0) ? NEG : prevs[k] + tp[k];
                float hi = fmaxf(stay, move);
                float lo = fminf(stay, move);
                beta[k] = em[k] + hi + __logf(1.f + __expf(lo - hi));
            }
        }
    }
}

extern "C" void kernel_launch(void* const* d_in, const int* in_sizes, int n_in,
                              void* d_out, int out_size) {
    const float* lp  = (const float*)d_in[0];
    const float* tr  = (const float*)d_in[1];
    const int*   tgt = (const int*)d_in[2];
    const int*   il  = (const int*)d_in[3];
    const int*   tl  = (const int*)d_in[4];
    (void)in_sizes; (void)n_in; (void)out_size;

    asg_main<<<NFCC * CSZ + CSZ, NTHR>>>(lp, tr, tgt, il, tl, (float*)d_out);
}

// round 15
// speedup vs baseline: 1.3343x; 1.3343x over previous
#include <cuda_runtime.h>
#include <cstdint>

// ASG loss = FCC (log-partition over all paths) - FAC (forced alignment).
// T=512, B=32, V=512, L=128 (fixed by dataset).
//
// FCC: unnormalized probability recursion v' = exp(lp) * (E v), E in regs.
// Cluster of 8 CTAs per 2 batches. PULL exchange: producers write their 64
// own rows LOCALLY (plain st.shared); the per-step barrier carries only
// one release-arrive per (warp, rank): 128 arrivals/dest/step, count-based
// mbarrier (no expect_tx, no remote data stores). Consumers read peers' v
// slices directly with ld.shared::cluster inside Phase A, where DSMEM
// latency overlaps with FMA issue across warps. Each Phase-A load hits
// exactly ONE rank uniformly across lanes (E re-gathered to j=64rk+2lane).
// Backpressure is automatic: buffer reuse is gated by the count barrier,
// and peers arrive only after their reads of that buffer.
// FAC: separate CTAs, 1 warp/batch, register-resident.

namespace {
constexpr int T_ = 512, B_ = 32, V_ = 512, L_ = 128;
constexpr int CSZ = 8;      // cluster size
constexpr int ISL = 64;     // i-rows per CTA
constexpr int NTHR = 512;
constexpr int NFCC = 16;    // FCC clusters (2 batches each)
constexpr float NEG = -1000000000.0f;
constexpr unsigned ARRIVALS = 16u * CSZ;   // 16 warps x 8 CTAs per phase
}

__device__ float g_fcc[B_];
__device__ float g_fac[B_];
__device__ unsigned g_done[B_];   // parity counter, never reset

static __device__ __forceinline__ unsigned cta_rank() {
    unsigned r; asm("mov.u32 %0, %%cluster_ctarank;" : "=r"(r)); return r;
}
static __device__ __forceinline__ unsigned su32(const void* p) {
    unsigned a;
    asm("{ .reg .u64 t; cvta.to.shared.u64 t, %1; cvt.u32.u64 %0, t; }"
        : "=r"(a) : "l"(p));
    return a;
}
static __device__ __forceinline__ unsigned mapa_r(unsigned a, unsigned r) {
    unsigned o;
    asm("mapa.shared::cluster.u32 %0, %1, %2;" : "=r"(o) : "r"(a), "r"(r));
    return o;
}
static __device__ __forceinline__ void csync() {
    asm volatile("barrier.cluster.arrive.aligned;" ::: "memory");
    asm volatile("barrier.cluster.wait.aligned;" ::: "memory");
}
static __device__ __forceinline__ void mbar_init(unsigned a, unsigned cnt) {
    asm volatile("mbarrier.init.shared.b64 [%0], %1;" :: "r"(a), "r"(cnt) : "memory");
}
static __device__ __forceinline__ void mbar_arrive_remote(unsigned a) {
    asm volatile("mbarrier.arrive.release.cluster.shared::cluster.b64 _, [%0];"
                 :: "r"(a) : "memory");
}
static __device__ __forceinline__ void mbar_wait(unsigned a, unsigned parity) {
    unsigned done;
    asm volatile(
        "{\n\t.reg .pred p;\n\t"
        "mbarrier.try_wait.parity.acquire.cluster.shared::cta.b64 p, [%1], %2;\n\t"
        "selp.b32 %0, 1, 0, p;\n\t}"
        : "=r"(done) : "r"(a), "r"(parity) : "memory");
    if (!done) {
        asm volatile(
            "{\n\t.reg .pred P1;\n\t"
            "WL_%=:\n\t"
            "mbarrier.try_wait.parity.acquire.cluster.shared::cta.b64 P1, [%0], %1, 0x989680;\n\t"
            "@P1 bra.uni WD_%=;\n\t"
            "bra.uni WL_%=;\n\t"
            "WD_%=:\n\t}"
            :: "r"(a), "r"(parity) : "memory");
    }
}
static __device__ __forceinline__ unsigned long long ld_dsmem64(unsigned a) {
    unsigned long long v;
    asm volatile("ld.shared::cluster.b64 %0, [%1];" : "=l"(v) : "r"(a));
    return v;
}
static __device__ __forceinline__ unsigned long long fma2(
    unsigned long long a, unsigned long long b, unsigned long long c) {
    unsigned long long d;
    asm("fma.rn.f32x2 %0, %1, %2, %3;" : "=l"(d) : "l"(a), "l"(b), "l"(c));
    return d;
}
static __device__ __forceinline__ unsigned long long packf2(float lo, float hi) {
    unsigned long long d;
    asm("mov.b64 %0, {%1,%2};" : "=l"(d) : "f"(lo), "f"(hi));
    return d;
}
static __device__ __forceinline__ float pairsum(unsigned long long a) {
    float lo, hi;
    asm("mov.b64 {%0,%1}, %2;" : "=f"(lo), "=f"(hi) : "l"(a));
    return lo + hi;
}
// Merge-reduce step: combine two per-lane partial values; lanes with
// (lane & m) carry the 'b' index forward.
static __device__ __forceinline__ float mrg(float a, float b, int m, int lane) {
    float send = (lane & m) ? a : b;
    float keep = (lane & m) ? b : a;
    return keep + __shfl_xor_sync(~0u, send, m);
}

// Second arriver (parity odd) of {fcc, fac} writes the output.
static __device__ __forceinline__ void publish(int b, float val, bool is_fcc,
                                               float* __restrict__ out) {
    if (is_fcc) g_fcc[b] = val; else g_fac[b] = val;
    __threadfence();
    unsigned old = atomicAdd(&g_done[b], 1u);
    if (old & 1u) {
        __threadfence();
        out[b] = g_fcc[b] - g_fac[b];
    }
}

__global__ void __launch_bounds__(NTHR, 1) __cluster_dims__(CSZ, 1, 1)
asg_main(const float* __restrict__ lp, const float* __restrict__ tr,
         const int* __restrict__ tgt, const int* __restrict__ ilen,
         const int* __restrict__ tlen, float* __restrict__ out)
{
    __shared__ __align__(16) float s_u[2][2][ISL];       // OWN slice only
    __shared__ __align__(8) unsigned long long s_mbar[2];

    const int tid  = threadIdx.x;
    const int lane = tid & 31;
    const int wid  = tid >> 5;
    const int cid  = (int)blockIdx.x >> 3;

    if (cid < NFCC) {
        // =============================== FCC ===============================
        const unsigned r = cta_rank();
        const int b0 = 2 * cid, b1 = 2 * cid + 1;
        const int len0 = ilen[b0], len1 = ilen[b1];

        // Value lanes (lane&3)==0 end with the total for idx = lane>>2 =
        // rr*2 + bb after the merge tree (same as the 825us kernel).
        const bool isp = (lane & 3) == 0;
        const int idx = lane >> 2;
        const int prr = idx >> 1, pbb = idx & 1;
        const int prl  = wid * 4 + prr;                  // local row (0..63)
        const int prow = (int)r * ISL + prl;             // global row

        const unsigned ubase = su32(&s_u[0][0][0]);
        const unsigned mloc0 = su32(&s_mbar[0]);
        unsigned base[CSZ];
        #pragma unroll
        for (int rk = 0; rk < CSZ; ++rk) base[rk] = mapa_r(ubase, (unsigned)rk);
        const unsigned mbar_rk = mapa_r(mloc0, (unsigned)(lane & 7));

        if (tid == 0) {
            mbar_init(mloc0, ARRIVALS);
            mbar_init(mloc0 + 8, ARRIVALS);
        }

        // E registers: warp w owns rows r*64+4w+rr (rr<4); lane owns
        // j in {64*rk + 2*lane, +1} for rk = 0..7 (one rank per rk).
        unsigned long long e2[32];
        #pragma unroll
        for (int rr = 0; rr < 4; ++rr) {
            const int row = (int)r * ISL + wid * 4 + rr;
            #pragma unroll
            for (int rk = 0; rk < CSZ; ++rk) {
                float2 v2 = *(const float2*)(tr + (size_t)row * V_ + 64 * rk + 2 * lane);
                e2[rr * 8 + rk] = packf2(__expf(v2.x), __expf(v2.y));
            }
        }

        // v_0: each CTA writes only its own 64-row slice (both batches).
        if (tid < 128) {
            const int bb = tid >> 6, ii = tid & 63;
            s_u[0][bb][ii] = __expf(lp[(size_t)(bb ? b1 : b0) * V_ + (int)r * ISL + ii]);
        }
        __syncthreads();
        csync();   // peers' mbar init + v0 slices visible cluster-wide

        for (int t = 0; t < T_; ++t) {
            const int buf = t & 1;

            // Prefetch exp(lp[t+1]) for this lane's (row,batch), before wait
            float el = 0.f;
            if (isp && t + 1 < T_)
                el = __expf(lp[((size_t)(t + 1) * B_ + (pbb ? b1 : b0)) * V_ + prow]);

            if (t) mbar_wait(mloc0 + (unsigned)buf * 8, (unsigned)(((t - 1) >> 1) & 1));

            // Score capture (once per batch): pull all slices, sum, log.
            if (r == 0 && (wid == 8 || wid == 9)) {
                const int bs = wid - 8;
                if (t == (bs ? len1 : len0) - 1) {
                    const unsigned off = ((unsigned)(buf * 2 + bs) * ISL + 2u * lane) * 4u;
                    float sc = 0.f;
                    #pragma unroll
                    for (int rk = 0; rk < CSZ; ++rk)
                        sc += pairsum(ld_dsmem64(base[rk] + off));
                    #pragma unroll
                    for (int mk = 16; mk; mk >>= 1) sc += __shfl_xor_sync(~0u, sc, mk);
                    if (lane == 0) publish(bs ? b1 : b0, logf(sc), true, out);
                }
            }
            if (t == T_ - 1) break;

            // Phase A: pull v slices from each rank and dot against E.
            // Per batch: 8 uniform-rank ld.shared::cluster.b64 (MLP=8).
            float f[8];
            #pragma unroll
            for (int bb = 0; bb < 2; ++bb) {
                const unsigned off = ((unsigned)(buf * 2 + bb) * ISL + 2u * lane) * 4u;
                unsigned long long vb[CSZ];
                #pragma unroll
                for (int rk = 0; rk < CSZ; ++rk)
                    vb[rk] = ld_dsmem64(base[rk] + off);
                unsigned long long acc[4] = {0ull, 0ull, 0ull, 0ull};
                #pragma unroll
                for (int rk = 0; rk < CSZ; ++rk) {
                    #pragma unroll
                    for (int rr = 0; rr < 4; ++rr)
                        acc[rr] = fma2(e2[rr * 8 + rk], vb[rk], acc[rr]);
                }
                #pragma unroll
                for (int rr = 0; rr < 4; ++rr) f[rr * 2 + bb] = pairsum(acc[rr]);
            }

            // Merge-tree: lane (idx<<2) ends with total for f[idx] (idx=rr*2+bb)
            float g0 = mrg(f[0], f[4], 16, lane);
            float g1 = mrg(f[1], f[5], 16, lane);
            float g2 = mrg(f[2], f[6], 16, lane);
            float g3 = mrg(f[3], f[7], 16, lane);
            float h0 = mrg(g0, g2, 8, lane);
            float h1 = mrg(g1, g3, 8, lane);
            float s  = mrg(h0, h1, 4, lane);
            s += __shfl_xor_sync(~0u, s, 2);
            s += __shfl_xor_sync(~0u, s, 1);

            // Phase B: LOCAL write of v'; then one release-arrive per rank
            // from lanes 0..7 (after __syncwarp for intra-warp HB).
            const int nbuf = buf ^ 1;
            if (isp) s_u[nbuf][pbb][prl] = el * s;
            __syncwarp();
            if (lane < 8) mbar_arrive_remote(mbar_rk + (unsigned)nbuf * 8u);
        }
        csync();   // no CTA exits while peers may still read its SMEM
    } else {
        // =============================== FAC ===============================
        if (wid >= 4) return;
        const int b = ((int)blockIdx.x - NFCC * CSZ) * 4 + wid;   // 0..31
        const int il = ilen[b], tl = tlen[b];

        int tg[4];
        #pragma unroll
        for (int k = 0; k < 4; ++k) tg[k] = tgt[b * L_ + lane * 4 + k];

        float ts[4], tp[4];
        #pragma unroll
        for (int k = 0; k < 4; ++k) ts[k] = tr[tg[k] * V_ + tg[k]];
        const int tprev = __shfl_up_sync(~0u, tg[3], 1);
        tp[0] = tr[tg[0] * V_ + tprev];           // garbage on lane 0, never used
        tp[1] = tr[tg[1] * V_ + tg[0]];
        tp[2] = tr[tg[2] * V_ + tg[1]];
        tp[3] = tr[tg[3] * V_ + tg[2]];

        float beta[4];
        #pragma unroll
        for (int k = 0; k < 4; ++k)
            beta[k] = (lane == 0 && k == 0) ? lp[(size_t)b * V_ + tg[0]] : NEG;

        float emn[4];
        #pragma unroll
        for (int k = 0; k < 4; ++k)
            emn[k] = lp[((size_t)1 * B_ + b) * V_ + tg[k]];

        for (int t = 0; t < T_; ++t) {
            if (t == il - 1) {
                const int lsel = tl - 1;
                if (lane == (lsel >> 2)) publish(b, beta[lsel & 3], false, out);
            }
            if (t == T_ - 1) break;

            float em[4];
            #pragma unroll
            for (int k = 0; k < 4; ++k) em[k] = emn[k];
            if (t + 2 < T_) {
                #pragma unroll
                for (int k = 0; k < 4; ++k)
                    emn[k] = lp[((size_t)(t + 2) * B_ + b) * V_ + tg[k]];
            }

            const float bprev = __shfl_up_sync(~0u, beta[3], 1);
            float prevs[4] = {bprev, beta[0], beta[1], beta[2]};
            #pragma unroll
            for (int k = 0; k < 4; ++k) {
                float stay = beta[k] + ts[k];
                float move = (lane == 0 && k == 0) ? NEG : prevs[k] + tp[k];
                float hi = fmaxf(stay, move);
                float lo = fminf(stay, move);
                beta[k] = em[k] + hi + __logf(1.f + __expf(lo - hi));
            }
        }
    }
}

extern "C" void kernel_launch(void* const* d_in, const int* in_sizes, int n_in,
                              void* d_out, int out_size) {
    const float* lp  = (const float*)d_in[0];
    const float* tr  = (const float*)d_in[1];
    const int*   tgt = (const int*)d_in[2];
    const int*   il  = (const int*)d_in[3];
    const int*   tl  = (const int*)d_in[4];
    (void)in_sizes; (void)n_in; (void)out_size;

    asg_main<<<NFCC * CSZ + CSZ, NTHR>>>(lp, tr, tgt, il, tl, (float*)d_out);
}

// round 16
// speedup vs baseline: 4.8967x; 3.6698x over previous
#include <cuda_runtime.h>
#include <cstdint>

// ASG loss = FCC (log-partition over all paths) - FAC (forced alignment).
// T=512, B=32, V=512, L=128 (fixed by dataset).
//
// FCC: unnormalized probability recursion v' = exp(lp) * (E v), E in regs.
// Cluster of 8 CTAs per 2 batches. Per-step exchange: SELF-SIGNALING
// st.async scalar stores carrying mbarrier complete_tx credits — protocol
// byte-identical to the 825us best (2 tx-barriers, expect_tx=4096B,
// parity ((t-1)>>1)&1, re-arm after consume, 1024 msgs/dest/step).
// ONLY change vs that kernel: the merge tree leaves the SAME total on all
// 4 lanes of a quad, so the 8-rank push is split across lanes 4i (ranks
// 0-3) and 4i+1 (ranks 4-7), halving the serial STAS tail per lane.
// FAC: separate CTAs, 1 warp/batch, register-resident.

namespace {
constexpr int T_ = 512, B_ = 32, V_ = 512, L_ = 128;
constexpr int CSZ = 8;      // cluster size
constexpr int ISL = 64;     // i-rows per CTA
constexpr int NTHR = 512;
constexpr int NFCC = 16;    // FCC clusters (2 batches each)
constexpr float NEG = -1000000000.0f;
constexpr unsigned FILL_BYTES = 2u * V_ * 4u;   // 4096 B per fill
}

__device__ float g_fcc[B_];
__device__ float g_fac[B_];
__device__ unsigned g_done[B_];   // parity counter, never reset

static __device__ __forceinline__ unsigned cta_rank() {
    unsigned r; asm("mov.u32 %0, %%cluster_ctarank;" : "=r"(r)); return r;
}
static __device__ __forceinline__ unsigned su32(const void* p) {
    unsigned a;
    asm("{ .reg .u64 t; cvta.to.shared.u64 t, %1; cvt.u32.u64 %0, t; }"
        : "=r"(a) : "l"(p));
    return a;
}
static __device__ __forceinline__ unsigned mapa_r(unsigned a, unsigned r) {
    unsigned o;
    asm("mapa.shared::cluster.u32 %0, %1, %2;" : "=r"(o) : "r"(a), "r"(r));
    return o;
}
static __device__ __forceinline__ void csync() {
    asm volatile("barrier.cluster.arrive.aligned;" ::: "memory");
    asm volatile("barrier.cluster.wait.aligned;" ::: "memory");
}
static __device__ __forceinline__ void mbar_init(unsigned a, unsigned cnt) {
    asm volatile("mbarrier.init.shared.b64 [%0], %1;" :: "r"(a), "r"(cnt) : "memory");
}
static __device__ __forceinline__ void mbar_expect(unsigned a, unsigned tx) {
    asm volatile("mbarrier.arrive.expect_tx.shared.b64 _, [%0], %1;"
                 :: "r"(a), "r"(tx) : "memory");
}
// Self-signaling remote store: data lands in peer SMEM, credits 4 bytes on
// the peer's mbarrier when complete.
static __device__ __forceinline__ void st_async32(unsigned a, float v, unsigned mb) {
    asm volatile("st.async.shared::cluster.mbarrier::complete_tx::bytes.b32 [%0], %1, [%2];"
                 :: "r"(a), "r"(__float_as_uint(v)), "r"(mb) : "memory");
}
static __device__ __forceinline__ void mbar_wait(unsigned a, unsigned parity) {
    unsigned done;
    asm volatile(
        "{\n\t.reg .pred p;\n\t"
        "mbarrier.try_wait.parity.acquire.cluster.shared::cta.b64 p, [%1], %2;\n\t"
        "selp.b32 %0, 1, 0, p;\n\t}"
        : "=r"(done) : "r"(a), "r"(parity) : "memory");
    if (!done) {
        asm volatile(
            "{\n\t.reg .pred P1;\n\t"
            "WL_%=:\n\t"
            "mbarrier.try_wait.parity.acquire.cluster.shared::cta.b64 P1, [%0], %1, 0x989680;\n\t"
            "@P1 bra.uni WD_%=;\n\t"
            "bra.uni WL_%=;\n\t"
            "WD_%=:\n\t}"
            :: "r"(a), "r"(parity) : "memory");
    }
}
static __device__ __forceinline__ unsigned long long fma2(
    unsigned long long a, unsigned long long b, unsigned long long c) {
    unsigned long long d;
    asm("fma.rn.f32x2 %0, %1, %2, %3;" : "=l"(d) : "l"(a), "l"(b), "l"(c));
    return d;
}
static __device__ __forceinline__ unsigned long long packf2(float lo, float hi) {
    unsigned long long d;
    asm("mov.b64 %0, {%1,%2};" : "=l"(d) : "f"(lo), "f"(hi));
    return d;
}
static __device__ __forceinline__ float pairsum(unsigned long long a) {
    float lo, hi;
    asm("mov.b64 {%0,%1}, %2;" : "=f"(lo), "=f"(hi) : "l"(a));
    return lo + hi;
}
// Merge-reduce step: combine two per-lane partial values; lanes with
// (lane & m) carry the 'b' index forward.
static __device__ __forceinline__ float mrg(float a, float b, int m, int lane) {
    float send = (lane & m) ? a : b;
    float keep = (lane & m) ? b : a;
    return keep + __shfl_xor_sync(~0u, send, m);
}

// Second arriver (parity odd) of {fcc, fac} writes the output.
static __device__ __forceinline__ void publish(int b, float val, bool is_fcc,
                                               float* __restrict__ out) {
    if (is_fcc) g_fcc[b] = val; else g_fac[b] = val;
    __threadfence();
    unsigned old = atomicAdd(&g_done[b], 1u);
    if (old & 1u) {
        __threadfence();
        out[b] = g_fcc[b] - g_fac[b];
    }
}

__global__ void __launch_bounds__(NTHR, 1) __cluster_dims__(CSZ, 1, 1)
asg_main(const float* __restrict__ lp, const float* __restrict__ tr,
         const int* __restrict__ tgt, const int* __restrict__ ilen,
         const int* __restrict__ tlen, float* __restrict__ out)
{
    __shared__ __align__(16) float s_u[2][2][V_];        // double-buffered v
    __shared__ __align__(8) unsigned long long s_mbar[2];

    const int tid  = threadIdx.x;
    const int lane = tid & 31;
    const int wid  = tid >> 5;
    const int cid  = (int)blockIdx.x >> 3;

    if (cid < NFCC) {
        // =============================== FCC ===============================
        const unsigned r = cta_rank();
        const int b0 = 2 * cid, b1 = 2 * cid + 1;
        const int len0 = ilen[b0], len1 = ilen[b1];

        // Quad idx = lane>>2 selects (row rr = idx>>1, batch bb = idx&1).
        // After the merge tree all 4 lanes of a quad hold the same total:
        // lanes 4i and 4i+1 split the 8-rank push (4 STAS each).
        const bool isel = (lane & 3) < 2;        // el loaders / pushers
        const int idx = lane >> 2;
        const int prr = idx >> 1, pbb = idx & 1;
        const int prow = (int)r * ISL + wid * 4 + prr;   // this quad's row
        const int half = lane & 1;               // 0: ranks 0-3, 1: ranks 4-7

        const unsigned ubase  = su32(&s_u[0][0][0]);
        const unsigned mloc0  = su32(&s_mbar[0]);
        const unsigned mdelta = mloc0 - ubase;
        unsigned pb[CSZ];
        #pragma unroll
        for (int rk = 0; rk < CSZ; ++rk) pb[rk] = mapa_r(ubase, (unsigned)rk);

        if (tid == 0) {
            mbar_init(mloc0, 1);
            mbar_init(mloc0 + 8, 1);
            mbar_expect(mloc0 + 8, FILL_BYTES);   // fill@t=0 targets mbar[1]
        }

        // E registers: warp w owns rows r*64 + 4w + rr (rr<4); lane owns
        // j in {4*lane + 128k + m}: conflict-free interleaved map.
        unsigned long long e2[32];
        #pragma unroll
        for (int rr = 0; rr < 4; ++rr) {
            const int row = (int)r * ISL + wid * 4 + rr;
            #pragma unroll
            for (int k = 0; k < 4; ++k) {
                float4 v4 = *(const float4*)(tr + (size_t)row * V_ + 4 * lane + 128 * k);
                e2[rr * 8 + 2 * k]     = packf2(__expf(v4.x), __expf(v4.y));
                e2[rr * 8 + 2 * k + 1] = packf2(__expf(v4.z), __expf(v4.w));
            }
        }

        // v_0 = exp(lp[0,b,:]); every CTA initializes buffer 0 locally.
        s_u[0][0][tid] = __expf(lp[(size_t)b0 * V_ + tid]);
        s_u[0][1][tid] = __expf(lp[(size_t)b1 * V_ + tid]);
        __syncthreads();
        csync();   // peers' mbar init + expect + buffers visible

        for (int t = 0; t < T_; ++t) {
            const int buf = t & 1;

            // Prefetch exp(lp[t+1]) for this quad's (row,batch), before wait
            float el = 0.f;
            if (isel && t + 1 < T_)
                el = __expf(lp[((size_t)(t + 1) * B_ + (pbb ? b1 : b0)) * V_ + prow]);

            if (t) mbar_wait(mloc0 + (unsigned)buf * 8, (unsigned)(((t - 1) >> 1) & 1));

            // Arm this mbar for its next fill (fill@t+1), after its consume
            if (tid == 0 && t + 3 <= T_)
                mbar_expect(mloc0 + (unsigned)buf * 8, FILL_BYTES);

            // Score capture (once per batch): lse(alpha_t) = log sum_j v_j
            if (r == 0 && (wid == 8 || wid == 9)) {
                const int bs = wid - 8;
                if (t == (bs ? len1 : len0) - 1) {
                    float s = 0.f;
                    #pragma unroll
                    for (int k = 0; k < 16; ++k) s += s_u[buf][bs][lane + 32 * k];
                    #pragma unroll
                    for (int mk = 16; mk; mk >>= 1) s += __shfl_xor_sync(~0u, s, mk);
                    if (lane == 0) publish(bs ? b1 : b0, logf(s), true, out);
                }
            }
            if (t == T_ - 1) break;

            // Phase A: complete dots for 4 rows x 2 batches, lanes split j
            unsigned long long acc[4][2];
            #pragma unroll
            for (int rr = 0; rr < 4; ++rr) { acc[rr][0] = 0ull; acc[rr][1] = 0ull; }
            #pragma unroll
            for (int k = 0; k < 4; ++k) {
                ulonglong2 q0 = *(const ulonglong2*)&s_u[buf][0][4 * lane + 128 * k];
                ulonglong2 q1 = *(const ulonglong2*)&s_u[buf][1][4 * lane + 128 * k];
                #pragma unroll
                for (int rr = 0; rr < 4; ++rr) {
                    acc[rr][0] = fma2(e2[rr * 8 + 2 * k],     q0.x, acc[rr][0]);
                    acc[rr][0] = fma2(e2[rr * 8 + 2 * k + 1], q0.y, acc[rr][0]);
                    acc[rr][1] = fma2(e2[rr * 8 + 2 * k],     q1.x, acc[rr][1]);
                    acc[rr][1] = fma2(e2[rr * 8 + 2 * k + 1], q1.y, acc[rr][1]);
                }
            }

            // Merge-tree: every lane of quad idx ends with the total for
            // f[idx] (idx = rr*2 + bb) after the final two xor rounds.
            float f[8];
            #pragma unroll
            for (int rr = 0; rr < 4; ++rr) {
                f[rr * 2]     = pairsum(acc[rr][0]);
                f[rr * 2 + 1] = pairsum(acc[rr][1]);
            }
            float g0 = mrg(f[0], f[4], 16, lane);
            float g1 = mrg(f[1], f[5], 16, lane);
            float g2 = mrg(f[2], f[6], 16, lane);
            float g3 = mrg(f[3], f[7], 16, lane);
            float h0 = mrg(g0, g2, 8, lane);
            float h1 = mrg(g1, g3, 8, lane);
            float s  = mrg(h0, h1, 4, lane);
            s += __shfl_xor_sync(~0u, s, 2);
            s += __shfl_xor_sync(~0u, s, 1);

            // Push v' = el * s: lane 4i sends ranks 0-3, lane 4i+1 ranks 4-7.
            if (isel) {
                const float v = el * s;
                const int nbuf = buf ^ 1;
                const unsigned off = ((unsigned)(nbuf * 2 + pbb) * V_ + (unsigned)prow) * 4u;
                const unsigned mboff = mdelta + (unsigned)nbuf * 8u;
                const int rk0 = half * 4;
                #pragma unroll
                for (int rk = 0; rk < 4; ++rk)
                    st_async32(pb[rk0 + rk] + off, v, pb[rk0 + rk] + mboff);
            }
        }
        csync();   // no CTA exits while peers may still write its SMEM
    } else {
        // =============================== FAC ===============================
        if (wid >= 4) return;
        const int b = ((int)blockIdx.x - NFCC * CSZ) * 4 + wid;   // 0..31
        const int il = ilen[b], tl = tlen[b];

        int tg[4];
        #pragma unroll
        for (int k = 0; k < 4; ++k) tg[k] = tgt[b * L_ + lane * 4 + k];

        float ts[4], tp[4];
        #pragma unroll
        for (int k = 0; k < 4; ++k) ts[k] = tr[tg[k] * V_ + tg[k]];
        const int tprev = __shfl_up_sync(~0u, tg[3], 1);
        tp[0] = tr[tg[0] * V_ + tprev];           // garbage on lane 0, never used
        tp[1] = tr[tg[1] * V_ + tg[0]];
        tp[2] = tr[tg[2] * V_ + tg[1]];
        tp[3] = tr[tg[3] * V_ + tg[2]];

        float beta[4];
        #pragma unroll
        for (int k = 0; k < 4; ++k)
            beta[k] = (lane == 0 && k == 0) ? lp[(size_t)b * V_ + tg[0]] : NEG;

        float emn[4];
        #pragma unroll
        for (int k = 0; k < 4; ++k)
            emn[k] = lp[((size_t)1 * B_ + b) * V_ + tg[k]];

        for (int t = 0; t < T_; ++t) {
            if (t == il - 1) {
                const int lsel = tl - 1;
                if (lane == (lsel >> 2)) publish(b, beta[lsel & 3], false, out);
            }
            if (t == T_ - 1) break;

            float em[4];
            #pragma unroll
            for (int k = 0; k < 4; ++k) em[k] = emn[k];
            if (t + 2 < T_) {
                #pragma unroll
                for (int k = 0; k < 4; ++k)
                    emn[k] = lp[((size_t)(t + 2) * B_ + b) * V_ + tg[k]];
            }

            const float bprev = __shfl_up_sync(~0u, beta[3], 1);
            float prevs[4] = {bprev, beta[0], beta[1], beta[2]};
            #pragma unroll
            for (int k = 0; k < 4; ++k) {
                float stay = beta[k] + ts[k];
                float move = (lane == 0 && k == 0) ? NEG : prevs[k] + tp[k];
                float hi = fmaxf(stay, move);
                float lo = fminf(stay, move);
                beta[k] = em[k] + hi + __logf(1.f + __expf(lo - hi));
            }
        }
    }
}

extern "C" void kernel_launch(void* const* d_in, const int* in_sizes, int n_in,
                              void* d_out, int out_size) {
    const float* lp  = (const float*)d_in[0];
    const float* tr  = (const float*)d_in[1];
    const int*   tgt = (const int*)d_in[2];
    const int*   il  = (const int*)d_in[3];
    const int*   tl  = (const int*)d_in[4];
    (void)in_sizes; (void)n_in; (void)out_size;

    asg_main<<<NFCC * CSZ + CSZ, NTHR>>>(lp, tr, tgt, il, tl, (float*)d_out);
}

// round 17
// speedup vs baseline: 4.9227x; 1.0053x over previous
#include <cuda_runtime.h>
#include <cstdint>

// ASG loss = FCC (log-partition over all paths) - FAC (forced alignment).
// T=512, B=32, V=512, L=128 (fixed by dataset).
//
// FCC: unnormalized recursion v' = exp(lp) o (E v), COLUMN-SPLIT:
// CTA r owns E[:, 64r:64r+64] in registers and the v slice [64r:64r+64).
// Per step: P_r = E[:,slice_r] * v[slice_r] (all-local compute, no input
// exchange, zero redundancy); reduce-scatter: warp w pushes its 32 rows of
// P_r to rank q=(r+w/2)&7 (self-signaling st.async, 128B/warp-store,
// 1792B/dest/step); receiver sums 8 partials for its 64 rows and applies
// exp(lp). Warps 0-1 own rank-local rows (plain st.shared) and do the sum.
// Score: one-time fenced global atomic reduce of slice sums at t=len-1.
// FAC: separate CTAs, 1 warp/batch, register-resident.

namespace {
constexpr int T_ = 512, B_ = 32, V_ = 512, L_ = 128;
constexpr int CSZ = 8;      // cluster size
constexpr int ISL = 64;     // i/j slice per CTA
constexpr int NTHR = 512;
constexpr int NFCC = 16;    // FCC clusters (2 batches each)
constexpr float NEG = -1000000000.0f;
constexpr unsigned FILL_BYTES = 7u * ISL * 2u * 4u;   // 3584 B (7 peers)
}

__device__ float g_fcc[B_];
__device__ float g_fac[B_];
__device__ unsigned g_done[B_];    // parity counter, never reset
__device__ float g_scsum[B_];      // score reduce accumulator (self-reset)
__device__ unsigned g_sccnt[B_];   // score reduce arrival counter

static __device__ __forceinline__ unsigned cta_rank() {
    unsigned r; asm("mov.u32 %0, %%cluster_ctarank;" : "=r"(r)); return r;
}
static __device__ __forceinline__ unsigned su32(const void* p) {
    unsigned a;
    asm("{ .reg .u64 t; cvta.to.shared.u64 t, %1; cvt.u32.u64 %0, t; }"
        : "=r"(a) : "l"(p));
    return a;
}
static __device__ __forceinline__ unsigned mapa_r(unsigned a, unsigned r) {
    unsigned o;
    asm("mapa.shared::cluster.u32 %0, %1, %2;" : "=r"(o) : "r"(a), "r"(r));
    return o;
}
static __device__ __forceinline__ void csync() {
    asm volatile("barrier.cluster.arrive.aligned;" ::: "memory");
    asm volatile("barrier.cluster.wait.aligned;" ::: "memory");
}
static __device__ __forceinline__ void mbar_init(unsigned a, unsigned cnt) {
    asm volatile("mbarrier.init.shared.b64 [%0], %1;" :: "r"(a), "r"(cnt) : "memory");
}
static __device__ __forceinline__ void mbar_expect(unsigned a, unsigned tx) {
    asm volatile("mbarrier.arrive.expect_tx.shared.b64 _, [%0], %1;"
                 :: "r"(a), "r"(tx) : "memory");
}
static __device__ __forceinline__ void st_async32(unsigned a, float v, unsigned mb) {
    asm volatile("st.async.shared::cluster.mbarrier::complete_tx::bytes.b32 [%0], %1, [%2];"
                 :: "r"(a), "r"(__float_as_uint(v)), "r"(mb) : "memory");
}
static __device__ __forceinline__ void mbar_wait(unsigned a, unsigned parity) {
    unsigned done;
    asm volatile(
        "{\n\t.reg .pred p;\n\t"
        "mbarrier.try_wait.parity.acquire.cluster.shared::cta.b64 p, [%1], %2;\n\t"
        "selp.b32 %0, 1, 0, p;\n\t}"
        : "=r"(done) : "r"(a), "r"(parity) : "memory");
    if (!done) {
        asm volatile(
            "{\n\t.reg .pred P1;\n\t"
            "WL_%=:\n\t"
            "mbarrier.try_wait.parity.acquire.cluster.shared::cta.b64 P1, [%0], %1, 0x989680;\n\t"
            "@P1 bra.uni WD_%=;\n\t"
            "bra.uni WL_%=;\n\t"
            "WD_%=:\n\t}"
            :: "r"(a), "r"(parity) : "memory");
    }
}
static __device__ __forceinline__ unsigned long long fma2(
    unsigned long long a, unsigned long long b, unsigned long long c) {
    unsigned long long d;
    asm("fma.rn.f32x2 %0, %1, %2, %3;" : "=l"(d) : "l"(a), "l"(b), "l"(c));
    return d;
}
static __device__ __forceinline__ unsigned long long addf2(
    unsigned long long a, unsigned long long b) {
    unsigned long long d;
    asm("add.rn.f32x2 %0, %1, %2;" : "=l"(d) : "l"(a), "l"(b));
    return d;
}
static __device__ __forceinline__ unsigned long long packf2(float lo, float hi) {
    unsigned long long d;
    asm("mov.b64 %0, {%1,%2};" : "=l"(d) : "f"(lo), "f"(hi));
    return d;
}
static __device__ __forceinline__ float pairsum(unsigned long long a) {
    float lo, hi;
    asm("mov.b64 {%0,%1}, %2;" : "=f"(lo), "=f"(hi) : "l"(a));
    return lo + hi;
}

// Second arriver (parity odd) of {fcc, fac} writes the output.
static __device__ __forceinline__ void publish(int b, float val, bool is_fcc,
                                               float* __restrict__ out) {
    if (is_fcc) g_fcc[b] = val; else g_fac[b] = val;
    __threadfence();
    unsigned old = atomicAdd(&g_done[b], 1u);
    if (old & 1u) {
        __threadfence();
        out[b] = g_fcc[b] - g_fac[b];
    }
}

__global__ void __launch_bounds__(NTHR, 1) __cluster_dims__(CSZ, 1, 1)
asg_main(const float* __restrict__ lp, const float* __restrict__ tr,
         const int* __restrict__ tgt, const int* __restrict__ ilen,
         const int* __restrict__ tlen, float* __restrict__ out)
{
    __shared__ __align__(16) float s_v[2][2][ISL];          // own v slices
    __shared__ __align__(16) float s_in[2][2][CSZ][ISL];    // partial landing
    __shared__ __align__(8) unsigned long long s_mbar[2];

    const int tid  = threadIdx.x;
    const int lane = tid & 31;
    const int wid  = tid >> 5;
    const int cid  = (int)blockIdx.x >> 3;

    if (cid < NFCC) {
        // =============================== FCC ===============================
        const unsigned r = cta_rank();
        const int b0 = 2 * cid, b1 = 2 * cid + 1;
        const int len0 = ilen[b0], len1 = ilen[b1];

        // Warp w computes P rows for rank q=(r+w/2)&7, half h=w&1:
        // global row grow = 64q + 32h + lane. Warps 0,1 -> own rank (local).
        const int q    = ((int)r + (wid >> 1)) & 7;
        const int half = wid & 1;
        const int grow = 64 * q + 32 * half + lane;
        const bool own = (q == (int)r);           // wid 0,1
        const int srow = 32 * wid + lane;         // summer row (wid<2)

        const unsigned inbase = su32(&s_in[0][0][0][0]);
        const unsigned mloc   = su32(&s_mbar[0]);
        // remote dest for this lane's P (z=0, b=0); z adds 4096B, b1 adds 2048B
        const unsigned dst0 = mapa_r(inbase, (unsigned)q)
                            + (unsigned)((int)r * ISL + 32 * half + lane) * 4u;
        const unsigned mb_q = mapa_r(mloc, (unsigned)q);

        if (tid == 0) {
            mbar_init(mloc, 1);
            mbar_init(mloc + 8, 1);
            mbar_expect(mloc, FILL_BYTES);        // zone 0: first use t=1
            mbar_expect(mloc + 8, FILL_BYTES);    // zone 1: first use t=0
        }

        // E registers: row grow, own 64 columns [64r, 64r+64).
        unsigned long long e2[32];
        {
            const float* trow = tr + (size_t)grow * V_ + 64 * (int)r;
            #pragma unroll
            for (int m = 0; m < 16; ++m) {
                float4 v4 = *(const float4*)(trow + 4 * m);
                e2[2 * m]     = packf2(__expf(v4.x), __expf(v4.y));
                e2[2 * m + 1] = packf2(__expf(v4.z), __expf(v4.w));
            }
        }

        // v_0: own slice only.
        if (tid < 128) {
            const int bb = tid >> 6, l = tid & 63;
            s_v[0][bb][l] = __expf(lp[(size_t)(bb ? b1 : b0) * V_ + (int)r * ISL + l]);
        }
        __syncthreads();
        csync();   // mbar init/arming + v0 visible cluster-wide

        for (int t = 0; t < T_; ++t) {
            const int bu = t & 1;

            // Score: one-time global atomic reduce of slice sums (w2: b0, w3: b1)
            if (wid == 2 || wid == 3) {
                const int bs = wid - 2;
                if (t == (bs ? len1 : len0) - 1) {
                    float2 pv = *(const float2*)&s_v[bu][bs][2 * lane];
                    float sc = pv.x + pv.y;
                    #pragma unroll
                    for (int mk = 16; mk; mk >>= 1) sc += __shfl_xor_sync(~0u, sc, mk);
                    if (lane == 0) {
                        const int bb = bs ? b1 : b0;
                        atomicAdd(&g_scsum[bb], sc);
                        __threadfence();
                        unsigned c = atomicAdd(&g_sccnt[bb], 1u);
                        if ((c & 7u) == 7u) {
                            __threadfence();
                            float tot = atomicAdd(&g_scsum[bb], 0.f);
                            atomicExch(&g_scsum[bb], 0.f);   // reset for replay
                            publish(bb, logf(tot), true, out);
                        }
                    }
                }
            }
            if (t == T_ - 1) break;

            const int z = (t + 1) & 1;

            // el prefetch for summers (hidden under P compute)
            float el0 = 0.f, el1 = 0.f;
            if (wid < 2) {
                el0 = __expf(lp[((size_t)(t + 1) * B_ + b0) * V_ + (int)r * ISL + srow]);
                el1 = __expf(lp[((size_t)(t + 1) * B_ + b1) * V_ + (int)r * ISL + srow]);
            }

            // Phase A: P = E[:,slice_r] * v (all-local). 64 FMA2/lane.
            const ulonglong2* v0p = (const ulonglong2*)&s_v[bu][0][0];
            const ulonglong2* v1p = (const ulonglong2*)&s_v[bu][1][0];
            unsigned long long a0[4] = {0ull, 0ull, 0ull, 0ull};
            unsigned long long a1[4] = {0ull, 0ull, 0ull, 0ull};
            #pragma unroll
            for (int k = 0; k < 16; ++k) {
                ulonglong2 u = v0p[k], w = v1p[k];
                a0[k & 3] = fma2(e2[2 * k],     u.x, a0[k & 3]);
                a0[k & 3] = fma2(e2[2 * k + 1], u.y, a0[k & 3]);
                a1[k & 3] = fma2(e2[2 * k],     w.x, a1[k & 3]);
                a1[k & 3] = fma2(e2[2 * k + 1], w.y, a1[k & 3]);
            }
            const float P0 = pairsum(addf2(addf2(a0[0], a0[1]), addf2(a0[2], a0[3])));
            const float P1 = pairsum(addf2(addf2(a1[0], a1[1]), addf2(a1[2], a1[3])));

            // Push partials: own rank local, remote self-signaling.
            if (own) {
                s_in[z][0][(int)r][32 * half + lane] = P0;
                s_in[z][1][(int)r][32 * half + lane] = P1;
            } else {
                const unsigned d  = dst0 + (unsigned)z * 4096u;
                const unsigned mb = mb_q + (unsigned)z * 8u;
                st_async32(d, P0, mb);
                st_async32(d + 2048u, P1, mb);
            }

            // Phase B: summers (wid 0,1) wait for 7 peers, reduce, apply el.
            if (wid < 2) {
                mbar_wait(mloc + (unsigned)z * 8u, (unsigned)((t >> 1) & 1));
                if (tid == 0 && t <= T_ - 4)
                    mbar_expect(mloc + (unsigned)z * 8u, FILL_BYTES);
                float s0 = 0.f, s1 = 0.f;
                #pragma unroll
                for (int rk = 0; rk < CSZ; ++rk) {
                    s0 += s_in[z][0][rk][srow];
                    s1 += s_in[z][1][rk][srow];
                }
                s_v[z][0][srow] = el0 * s0;
                s_v[z][1][srow] = el1 * s1;
            }
            __syncthreads();   // releases all warps once v_{t+1} is ready
        }
        csync();   // no CTA exits while peers may still write its SMEM
    } else {
        // =============================== FAC ===============================
        if (wid >= 4) return;
        const int b = ((int)blockIdx.x - NFCC * CSZ) * 4 + wid;   // 0..31
        const int il = ilen[b], tl = tlen[b];

        int tg[4];
        #pragma unroll
        for (int k = 0; k < 4; ++k) tg[k] = tgt[b * L_ + lane * 4 + k];

        float ts[4], tp[4];
        #pragma unroll
        for (int k = 0; k < 4; ++k) ts[k] = tr[tg[k] * V_ + tg[k]];
        const int tprev = __shfl_up_sync(~0u, tg[3], 1);
        tp[0] = tr[tg[0] * V_ + tprev];           // garbage on lane 0, never used
        tp[1] = tr[tg[1] * V_ + tg[0]];
        tp[2] = tr[tg[2] * V_ + tg[1]];
        tp[3] = tr[tg[3] * V_ + tg[2]];

        float beta[4];
        #pragma unroll
        for (int k = 0; k < 4; ++k)
            beta[k] = (lane == 0 && k == 0) ? lp[(size_t)b * V_ + tg[0]] : NEG;

        float emn[4];
        #pragma unroll
        for (int k = 0; k < 4; ++k)
            emn[k] = lp[((size_t)1 * B_ + b) * V_ + tg[k]];

        for (int t = 0; t < T_; ++t) {
            if (t == il - 1) {
                const int lsel = tl - 1;
                if (lane == (lsel >> 2)) publish(b, beta[lsel & 3], false, out);
            }
            if (t == T_ - 1) break;

            float em[4];
            #pragma unroll
            for (int k = 0; k < 4; ++k) em[k] = emn[k];
            if (t + 2 < T_) {
                #pragma unroll
                for (int k = 0; k < 4; ++k)
                    emn[k] = lp[((size_t)(t + 2) * B_ + b) * V_ + tg[k]];
            }

            const float bprev = __shfl_up_sync(~0u, beta[3], 1);
            float prevs[4] = {bprev, beta[0], beta[1], beta[2]};
            #pragma unroll
            for (int k = 0; k < 4; ++k) {
                float stay = beta[k] + ts[k];
                float move = (lane == 0 && k == 0) ? NEG : prevs[k] + tp[k];
                float hi = fmaxf(stay, move);
                float lo = fminf(stay, move);
                beta[k] = em[k] + hi + __logf(1.f + __expf(lo - hi));
            }
        }
    }
}

extern "C" void kernel_launch(void* const* d_in, const int* in_sizes, int n_in,
                              void* d_out, int out_size) {
    const float* lp  = (const float*)d_in[0];
    const float* tr  = (const float*)d_in[1];
    const int*   tgt = (const int*)d_in[2];
    const int*   il  = (const int*)d_in[3];
    const int*   tl  = (const int*)d_in[4];
    (void)in_sizes; (void)n_in; (void)out_size;

    asg_main<<<NFCC * CSZ + CSZ, NTHR>>>(lp, tr, tgt, il, tl, (float*)d_out);
}